// round 1
// baseline (speedup 1.0000x reference)
#include <cuda_runtime.h>
#include <stdint.h>

// Problem constants (fixed by the reference)
#define NB 4096   // batch
#define ND 128    // hash dim
#define NCLS 80   // classes
#define EN 4      // ERROR_NUM
#define THREADS 128

// Scratch (no allocations allowed -> __device__ globals)
__device__ float g_partials[2 * NB];
__device__ int   g_cls[NB];

// ---------------------------------------------------------------------------
// Threefry-2x32, 20 rounds — exact match of jax/_src/prng.py threefry2x32
// ---------------------------------------------------------------------------
__device__ __forceinline__ void tf2x32(uint32_t k0, uint32_t k1,
                                       uint32_t x0, uint32_t x1,
                                       uint32_t& o0, uint32_t& o1) {
    uint32_t ks2 = k0 ^ k1 ^ 0x1BD11BDAu;
    x0 += k0; x1 += k1;
#define TF_R(r) { x0 += x1; x1 = __funnelshift_l(x1, x1, (r)); x1 ^= x0; }
#define TF_R4(a,b,c,d) TF_R(a) TF_R(b) TF_R(c) TF_R(d)
    TF_R4(13,15,26,6)   x0 += k1;  x1 += ks2 + 1u;
    TF_R4(17,29,16,24)  x0 += ks2; x1 += k0  + 2u;
    TF_R4(13,15,26,6)   x0 += k0;  x1 += k1  + 3u;
    TF_R4(17,29,16,24)  x0 += k1;  x1 += ks2 + 4u;
    TF_R4(13,15,26,6)   x0 += ks2; x1 += k0  + 5u;
#undef TF_R4
#undef TF_R
    o0 = x0; o1 = x1;
}

// Insert a key into a descending-sorted top-4 held in registers
#define INS4(kk)                                                              \
    { unsigned long long k_ = (kk);                                           \
      if (k_ > t3) {                                                          \
        if (k_ > t2) {                                                        \
          t3 = t2;                                                            \
          if (k_ > t1) { t2 = t1;                                             \
            if (k_ > t0) { t1 = t0; t0 = k_; } else t1 = k_;                  \
          } else t2 = k_;                                                     \
        } else t3 = k_;                                                       \
      }                                                                       \
    }

// ---------------------------------------------------------------------------
// Kernel 1: one-hot labels -> class id per row
// ---------------------------------------------------------------------------
__global__ void cls_kernel(const float* __restrict__ labels) {
    int r = blockIdx.x * blockDim.x + threadIdx.x;
    if (r < NB) {
        const float* L = labels + (size_t)r * NCLS;
        int c = 0;
        #pragma unroll 4
        for (int j = 0; j < NCLS; j++)
            if (L[j] > 0.5f) c = j;
        g_cls[r] = c;
    }
}

// ---------------------------------------------------------------------------
// Kernel 2: per (direction,row): threefry top-4 negative sampling + loss terms
//   blockIdx in [0, 2*NB): dir = blockIdx >> 12, row = blockIdx & 4095
//   dir 0: image->text (scores via ks1), dir 1: text->image (scores via ks2)
// ---------------------------------------------------------------------------
__global__ __launch_bounds__(THREADS) void triplet_kernel(
    const float* __restrict__ img, const float* __restrict__ txt) {

    __shared__ int   s_cls[NB];
    __shared__ unsigned long long s_top[16];
    __shared__ int   s_idx[EN];
    __shared__ float s_dist[EN + 1];

    const int tid = threadIdx.x;
    const int bid = blockIdx.x;
    const int dir = bid >> 12;
    const int row = bid & (NB - 1);

    for (int j = tid; j < NB; j += THREADS) s_cls[j] = g_cls[j];
    __syncthreads();

    // jax.random.key(42) -> (0,42); partitionable split (fold-like):
    //   ks_d = threefry2x32((0,42), (0, d))
    uint32_t ka, kb;
    tf2x32(0u, 42u, 0u, (uint32_t)dir, ka, kb);

    const int myc = s_cls[row];
    const uint32_t base = (uint32_t)row * (uint32_t)NB;

    // local top-4 (packed key: mantissa23 << 32 | (4095 - j))
    unsigned long long t0 = 0, t1 = 0, t2 = 0, t3 = 0;

    for (int j = tid; j < NB; j += THREADS) {
        if (s_cls[j] != myc) {
            uint32_t o0, o1;
            // partitionable random_bits: counts = (hi,lo) of 64-bit flat iota;
            // hi == 0 here; bits = o0 ^ o1
            tf2x32(ka, kb, 0u, base + (uint32_t)j, o0, o1);
            uint32_t m = (o0 ^ o1) >> 9;   // 23-bit mantissa; monotone in uniform
            unsigned long long key =
                ((unsigned long long)m << 32) |
                (unsigned long long)(uint32_t)(NB - 1 - j);
            INS4(key);
        }
    }

    // warp butterfly merge of sorted-4 lists
    #pragma unroll
    for (int off = 16; off; off >>= 1) {
        unsigned long long p0 = __shfl_xor_sync(0xffffffffu, t0, off);
        unsigned long long p1 = __shfl_xor_sync(0xffffffffu, t1, off);
        unsigned long long p2 = __shfl_xor_sync(0xffffffffu, t2, off);
        unsigned long long p3 = __shfl_xor_sync(0xffffffffu, t3, off);
        INS4(p0); INS4(p1); INS4(p2); INS4(p3);
    }

    const int wid = tid >> 5, lane = tid & 31;
    if (lane == 0) {
        s_top[wid * 4 + 0] = t0; s_top[wid * 4 + 1] = t1;
        s_top[wid * 4 + 2] = t2; s_top[wid * 4 + 3] = t3;
    }
    __syncthreads();

    if (tid == 0) {
        t0 = s_top[0]; t1 = s_top[1]; t2 = s_top[2]; t3 = s_top[3];
        #pragma unroll
        for (int k = 4; k < 16; k++) INS4(s_top[k]);
        s_idx[0] = NB - 1 - (int)(uint32_t)(t0 & 0xffffffffu);
        s_idx[1] = NB - 1 - (int)(uint32_t)(t1 & 0xffffffffu);
        s_idx[2] = NB - 1 - (int)(uint32_t)(t2 & 0xffffffffu);
        s_idx[3] = NB - 1 - (int)(uint32_t)(t3 & 0xffffffffu);
    }
    __syncthreads();

    // distances: warp w -> negative w; warp 0 also does the positive
    const float* a  = (dir ? txt : img) + (size_t)row * ND;
    const float* bb = dir ? img : txt;

    {
        const float* b = bb + (size_t)s_idx[wid] * ND;
        float s = 0.0f;
        #pragma unroll
        for (int d = lane; d < ND; d += 32) {
            float df = a[d] - b[d];
            s = fmaf(df, df, s);
        }
        #pragma unroll
        for (int off = 16; off; off >>= 1)
            s += __shfl_xor_sync(0xffffffffu, s, off);
        if (lane == 0) s_dist[wid] = sqrtf(s);
    }
    if (wid == 0) {
        const float* b = bb + (size_t)row * ND;
        float s = 0.0f;
        #pragma unroll
        for (int d = lane; d < ND; d += 32) {
            float df = a[d] - b[d];
            s = fmaf(df, df, s);
        }
        #pragma unroll
        for (int off = 16; off; off >>= 1)
            s += __shfl_xor_sync(0xffffffffu, s, off);
        if (lane == 0) s_dist[EN] = sqrtf(s);
    }
    __syncthreads();

    if (tid == 0) {
        float pos = s_dist[EN];
        float acc = 0.0f;
        #pragma unroll
        for (int k = 0; k < EN; k++)
            acc += fmaxf(pos - s_dist[k] + 1.0f, 0.0f);
        g_partials[bid] = acc;
    }
}

// ---------------------------------------------------------------------------
// Kernel 3: deterministic reduction -> loss = sum / (NB*EN)
// ---------------------------------------------------------------------------
__global__ void reduce_kernel(float* __restrict__ out) {
    __shared__ float s[256];
    int tid = threadIdx.x;
    float v = 0.0f;
    for (int i = tid; i < 2 * NB; i += 256) v += g_partials[i];
    s[tid] = v;
    __syncthreads();
    #pragma unroll
    for (int off = 128; off; off >>= 1) {
        if (tid < off) s[tid] += s[tid + off];
        __syncthreads();
    }
    if (tid == 0) out[0] = s[0] / (float)(NB * EN);
}

// ---------------------------------------------------------------------------
extern "C" void kernel_launch(void* const* d_in, const int* in_sizes, int n_in,
                              void* d_out, int out_size) {
    (void)in_sizes; (void)n_in; (void)out_size;
    const float* img    = (const float*)d_in[0];  // image_hash [4096,128]
    const float* txt    = (const float*)d_in[1];  // text_hash  [4096,128]
    const float* labels = (const float*)d_in[2];  // labels     [4096,80]
    float* out = (float*)d_out;

    cls_kernel<<<NB / 128, 128>>>(labels);
    triplet_kernel<<<2 * NB, THREADS>>>(img, txt);
    reduce_kernel<<<1, 256>>>(out);
}